// round 14
// baseline (speedup 1.0000x reference)
#include <cuda_runtime.h>
#include <cuda_bf16.h>
#include <cstdint>

// Problem constants
#define BB 2
#define TT 2048
#define DM 1024
#define NH 16
#define HS 64
#define QKVW 3072
#define CHUNK 64
#define NCK (TT / CHUNK)
#define NBH (BB * NH)
#define STSZ (HS * HS + HS)
#define PAD 68
#define P72 72

// Scratch
__device__ float g_qkv[(size_t)BB * TT * QKVW];
__device__ float g_state[(size_t)NBH * NCK * STSZ];
__device__ __nv_bfloat16 g_xhi[(size_t)BB * TT * DM];
__device__ __nv_bfloat16 g_xlo[(size_t)BB * TT * DM];
__device__ __nv_bfloat16 g_wqh[(size_t)QKVW * DM];
__device__ __nv_bfloat16 g_wql[(size_t)QKVW * DM];
__device__ __nv_bfloat16 g_woh[(size_t)DM * DM];
__device__ __nv_bfloat16 g_wol[(size_t)DM * DM];
__device__ __nv_bfloat16 g_xoh[(size_t)BB * TT * DM];
__device__ __nv_bfloat16 g_xol[(size_t)BB * TT * DM];

// ===========================================================================
// Helpers
// ===========================================================================
__device__ __forceinline__ uint32_t smem_u32(const void* p) {
    uint32_t a;
    asm("{ .reg .u64 t; cvta.to.shared.u64 t, %1; cvt.u32.u64 %0, t; }"
        : "=r"(a) : "l"(p));
    return a;
}

#define CP_ASYNC16(dst, src) \
    asm volatile("cp.async.cg.shared.global [%0], [%1], 16;" :: "r"(dst), "l"(src))
#define CP_COMMIT() asm volatile("cp.async.commit_group;" ::: "memory")
#define CP_WAIT1()  asm volatile("cp.async.wait_group 1;" ::: "memory")
#define CP_WAIT0()  asm volatile("cp.async.wait_group 0;" ::: "memory")

// split barriers: 256-thread CTA (512 arrivals) and 128-thread CTA (256)
#define BAR_ARRIVE() asm volatile("bar.arrive 1, 512;" ::: "memory")
#define BAR_SYNC()   asm volatile("bar.sync 1, 512;" ::: "memory")
#define BAR2_ARRIVE() asm volatile("bar.arrive 1, 256;" ::: "memory")
#define BAR2_SYNC()   asm volatile("bar.sync 1, 256;" ::: "memory")

__device__ __forceinline__ void ldsm_x4(uint32_t* r, uint32_t addr) {
    asm volatile("ldmatrix.sync.aligned.m8n8.x4.shared.b16 {%0,%1,%2,%3}, [%4];"
                 : "=r"(r[0]), "=r"(r[1]), "=r"(r[2]), "=r"(r[3]) : "r"(addr));
}

__device__ __forceinline__ void mma_bf16(float* c, const uint32_t* a, const uint32_t* b) {
    asm volatile(
        "mma.sync.aligned.m16n8k16.row.col.f32.bf16.bf16.f32 "
        "{%0,%1,%2,%3}, {%4,%5,%6,%7}, {%8,%9}, {%0,%1,%2,%3};"
        : "+f"(c[0]), "+f"(c[1]), "+f"(c[2]), "+f"(c[3])
        : "r"(a[0]), "r"(a[1]), "r"(a[2]), "r"(a[3]), "r"(b[0]), "r"(b[1]));
}

__device__ __forceinline__ void split2(float a, float b, uint32_t& hp, uint32_t& lp) {
    __nv_bfloat162 h = __floats2bfloat162_rn(a, b);
    float2 hf = __bfloat1622float2(h);
    __nv_bfloat162 l = __floats2bfloat162_rn(a - hf.x, b - hf.y);
    hp = *(uint32_t*)&h;
    lp = *(uint32_t*)&l;
}

__device__ __forceinline__ void split1(float v, __nv_bfloat16& h, __nv_bfloat16& l) {
    h = __float2bfloat16(v);
    l = __float2bfloat16(v - __bfloat162float(h));
}

// Generic split-bf16 MMA tile (pitch-72 bf16 smem, NT, K=64). Term-major.
template<int MI, int NB>
__device__ __forceinline__ void mm_tile(uint32_t Ahb, uint32_t Alb,
                                        uint32_t Bhb, uint32_t Blb,
                                        int wm, int wn,
                                        int a_mrow, int a_g, int b_nrow, int b_g,
                                        float acc[MI][2 * NB][4]) {
#pragma unroll
    for (int ks = 0; ks < 4; ks++) {
        uint32_t Ah[MI][4], Al[MI][4], Bh[2 * NB][2], Bl[2 * NB][2];
#pragma unroll
        for (int mi = 0; mi < MI; mi++) {
            uint32_t ao = (uint32_t)((wm + mi * 16 + a_mrow) * (P72 * 2) + (ks * 2 + a_g) * 16);
            ldsm_x4(Ah[mi], Ahb + ao);
            ldsm_x4(Al[mi], Alb + ao);
        }
#pragma unroll
        for (int nb = 0; nb < NB; nb++) {
            uint32_t bo = (uint32_t)((wn + nb * 16 + b_nrow) * (P72 * 2) + (ks * 2 + b_g) * 16);
            uint32_t t0[4], t1[4];
            ldsm_x4(t0, Bhb + bo);
            ldsm_x4(t1, Blb + bo);
            Bh[nb * 2][0] = t0[0]; Bh[nb * 2][1] = t0[1];
            Bh[nb * 2 + 1][0] = t0[2]; Bh[nb * 2 + 1][1] = t0[3];
            Bl[nb * 2][0] = t1[0]; Bl[nb * 2][1] = t1[1];
            Bl[nb * 2 + 1][0] = t1[2]; Bl[nb * 2 + 1][1] = t1[3];
        }
#pragma unroll
        for (int mi = 0; mi < MI; mi++)
#pragma unroll
            for (int ni = 0; ni < 2 * NB; ni++) mma_bf16(acc[mi][ni], Ah[mi], Bh[ni]);
#pragma unroll
        for (int mi = 0; mi < MI; mi++)
#pragma unroll
            for (int ni = 0; ni < 2 * NB; ni++) mma_bf16(acc[mi][ni], Ah[mi], Bl[ni]);
#pragma unroll
        for (int mi = 0; mi < MI; mi++)
#pragma unroll
            for (int ni = 0; ni < 2 * NB; ni++) mma_bf16(acc[mi][ni], Al[mi], Bh[ni]);
    }
}

// ---------------------------------------------------------------------------
// Prep: fp32 -> bf16 hi/lo split
// ---------------------------------------------------------------------------
__global__ __launch_bounds__(256) void split_f32(const float* __restrict__ src,
                                                 __nv_bfloat16* __restrict__ hi,
                                                 __nv_bfloat16* __restrict__ lo,
                                                 int n) {
    int i = (blockIdx.x * 256 + threadIdx.x) * 4;
    if (i >= n) return;
    float4 v = *(const float4*)(src + i);
    uint32_t h0, l0, h1, l1;
    split2(v.x, v.y, h0, l0);
    split2(v.z, v.w, h1, l1);
    *(uint2*)(hi + i) = make_uint2(h0, h1);
    *(uint2*)(lo + i) = make_uint2(l0, l1);
}

#define KT 32

// ===========================================================================
// GEMM-A: 128x128 tile, 256 threads, 2 CTA/SM. Best for gemm2 (256 CTAs = 1
// clean wave on 148 SMs x 2).
// ===========================================================================
#define TILE_B 8192
#define STAGE_B (4 * TILE_B)
#define NSTAGE 3
#define GEMM_SMEM_B (NSTAGE * STAGE_B)

__global__ __launch_bounds__(256) void gemm_bf16(const __nv_bfloat16* __restrict__ Ahi,
                                                 const __nv_bfloat16* __restrict__ Alo,
                                                 const __nv_bfloat16* __restrict__ Bhi,
                                                 const __nv_bfloat16* __restrict__ Blo,
                                                 float* __restrict__ C,
                                                 int M, int N, int K) {
    extern __shared__ char smraw[];
    const uint32_t sb = smem_u32(smraw);
    const int tid = threadIdx.x, wid = tid >> 5, lid = tid & 31;
    const int bm = blockIdx.y * 128, bn = blockIdx.x * 128;
    const int wm = (wid & 1) * 64, wn = (wid >> 1) * 32;
    const int NC = K / KT;

    const __nv_bfloat16* bases[4] = {Ahi, Alo, Bhi, Blo};

#define CP_STAGE(kc, s)                                                        \
    {                                                                          \
        uint32_t stb = sb + (s) * STAGE_B;                                     \
        _Pragma("unroll")                                                      \
        for (int it = 0; it < 8; it++) {                                       \
            int cid = it * 256 + tid;                                          \
            int tile = cid >> 9;                                               \
            int rem = cid & 511;                                               \
            int r = rem >> 2;                                                  \
            int g = rem & 3;                                                   \
            int row0 = (tile < 2) ? bm : bn;                                   \
            const __nv_bfloat16* src =                                         \
                bases[tile] + (size_t)(row0 + r) * K + (kc) * KT + g * 8;      \
            uint32_t dst = stb + tile * TILE_B + r * 64 +                      \
                           (((g ^ ((r >> 1) & 3))) << 4);                      \
            CP_ASYNC16(dst, src);                                              \
        }                                                                      \
        CP_COMMIT();                                                           \
    }

    float acc[4][4][4];
#pragma unroll
    for (int mi = 0; mi < 4; mi++)
#pragma unroll
        for (int ni = 0; ni < 4; ni++)
#pragma unroll
            for (int q = 0; q < 4; q++) acc[mi][ni][q] = 0.f;

    const int a_mrow = (lid < 16 ? lid : lid - 16);
    const int a_g    = (lid < 16 ? 0 : 1);
    const int b_q = lid & 7, b_g4 = lid >> 3;
    const int b_nrow = b_q + (b_g4 >> 1) * 8;
    const int b_g    = (b_g4 & 1);

    CP_STAGE(0, 0);
    CP_STAGE(1, 1);
    BAR_ARRIVE();

    for (int kc = 0; kc < NC; kc++) {
        if (kc < NC - 1) { CP_WAIT1(); } else { CP_WAIT0(); }
        BAR_SYNC();
        if (kc + 2 < NC) CP_STAGE(kc + 2, (kc + 2) % NSTAGE);

        const uint32_t stage = sb + (kc % NSTAGE) * STAGE_B;
#pragma unroll
        for (int ks = 0; ks < 2; ks++) {
            uint32_t Ah[4][4], Al[4][4], Bh[4][2], Bl[4][2];
#pragma unroll
            for (int mi = 0; mi < 4; mi++) {
                int row = wm + mi * 16 + a_mrow;
                int gran = ks * 2 + a_g;
                uint32_t addr = stage + row * 64 + ((gran ^ ((row >> 1) & 3)) << 4);
                ldsm_x4(Ah[mi], addr);
                ldsm_x4(Al[mi], addr + TILE_B);
            }
#pragma unroll
            for (int nb = 0; nb < 2; nb++) {
                int row = wn + nb * 16 + b_nrow;
                int gran = ks * 2 + b_g;
                uint32_t addr = stage + 2 * TILE_B + row * 64 +
                                ((gran ^ ((row >> 1) & 3)) << 4);
                uint32_t t[4];
                ldsm_x4(t, addr);
                Bh[nb * 2][0] = t[0]; Bh[nb * 2][1] = t[1];
                Bh[nb * 2 + 1][0] = t[2]; Bh[nb * 2 + 1][1] = t[3];
                ldsm_x4(t, addr + TILE_B);
                Bl[nb * 2][0] = t[0]; Bl[nb * 2][1] = t[1];
                Bl[nb * 2 + 1][0] = t[2]; Bl[nb * 2 + 1][1] = t[3];
            }
            if (ks == 1) BAR_ARRIVE();
#pragma unroll
            for (int mi = 0; mi < 4; mi++)
#pragma unroll
                for (int ni = 0; ni < 4; ni++) mma_bf16(acc[mi][ni], Ah[mi], Bh[ni]);
#pragma unroll
            for (int mi = 0; mi < 4; mi++)
#pragma unroll
                for (int ni = 0; ni < 4; ni++) mma_bf16(acc[mi][ni], Ah[mi], Bl[ni]);
#pragma unroll
            for (int mi = 0; mi < 4; mi++)
#pragma unroll
                for (int ni = 0; ni < 4; ni++) mma_bf16(acc[mi][ni], Al[mi], Bh[ni]);
        }
    }

    const int erow = lid >> 2, ecol = 2 * (lid & 3);
#pragma unroll
    for (int mi = 0; mi < 4; mi++) {
#pragma unroll
        for (int ni = 0; ni < 4; ni++) {
            float* c0 = C + (size_t)(bm + wm + mi * 16 + erow) * N + bn + wn + ni * 8 + ecol;
            *(float2*)c0 = make_float2(acc[mi][ni][0], acc[mi][ni][1]);
            *(float2*)(c0 + 8 * N) = make_float2(acc[mi][ni][2], acc[mi][ni][3]);
        }
    }
}

// ===========================================================================
// GEMM-B: 64x128 tile, 128 threads, 3 CTAs/SM. Best for gemm1 (1536 CTAs,
// 3.46 waves with higher tensor%).
// ===========================================================================
#define G1_AT 4096
#define G1_BT 8192
#define G1_STAGE 24576
#define G1_SMEM (3 * G1_STAGE)   // 73728 B

__global__ __launch_bounds__(128, 3) void gemm_bf16_64(
        const __nv_bfloat16* __restrict__ Ahi,
        const __nv_bfloat16* __restrict__ Alo,
        const __nv_bfloat16* __restrict__ Bhi,
        const __nv_bfloat16* __restrict__ Blo,
        float* __restrict__ C,
        int M, int N, int K) {
    extern __shared__ char smraw[];
    const uint32_t sb = smem_u32(smraw);
    const int tid = threadIdx.x, wid = tid >> 5, lid = tid & 31;
    const int bm = blockIdx.y * 64, bn = blockIdx.x * 128;
    const int wm = (wid & 1) * 32, wn = (wid >> 1) * 64;
    const int NC = K / KT;

#define CP_STAGE1(kc, s)                                                       \
    {                                                                          \
        uint32_t stb = sb + (s) * G1_STAGE;                                    \
        _Pragma("unroll")                                                      \
        for (int it = 0; it < 4; it++) {  /* A: 512 granules */                \
            int cid = it * 128 + tid;                                          \
            int comp = cid >> 8;                                               \
            int rem = cid & 255;                                               \
            int r = rem >> 2, g = rem & 3;                                     \
            const __nv_bfloat16* src = (comp ? Alo : Ahi) +                    \
                (size_t)(bm + r) * K + (kc) * KT + g * 8;                      \
            uint32_t dst = stb + comp * G1_AT + r * 64 +                       \
                           ((g ^ ((r >> 1) & 3)) << 4);                        \
            CP_ASYNC16(dst, src);                                              \
        }                                                                      \
        _Pragma("unroll")                                                      \
        for (int it = 0; it < 8; it++) {  /* B: 1024 granules */               \
            int cid = it * 128 + tid;                                          \
            int comp = cid >> 9;                                               \
            int rem = cid & 511;                                               \
            int r = rem >> 2, g = rem & 3;                                     \
            const __nv_bfloat16* src = (comp ? Blo : Bhi) +                    \
                (size_t)(bn + r) * K + (kc) * KT + g * 8;                      \
            uint32_t dst = stb + 2 * G1_AT + comp * G1_BT + r * 64 +           \
                           ((g ^ ((r >> 1) & 3)) << 4);                        \
            CP_ASYNC16(dst, src);                                              \
        }                                                                      \
        CP_COMMIT();                                                           \
    }

    float acc[2][8][4];
#pragma unroll
    for (int mi = 0; mi < 2; mi++)
#pragma unroll
        for (int ni = 0; ni < 8; ni++)
#pragma unroll
            for (int q = 0; q < 4; q++) acc[mi][ni][q] = 0.f;

    const int a_mrow = (lid < 16 ? lid : lid - 16);
    const int a_g    = (lid < 16 ? 0 : 1);
    const int b_q = lid & 7, b_g4 = lid >> 3;
    const int b_nrow = b_q + (b_g4 >> 1) * 8;
    const int b_g    = (b_g4 & 1);

    CP_STAGE1(0, 0);
    CP_STAGE1(1, 1);
    BAR2_ARRIVE();

    for (int kc = 0; kc < NC; kc++) {
        if (kc < NC - 1) { CP_WAIT1(); } else { CP_WAIT0(); }
        BAR2_SYNC();
        if (kc + 2 < NC) CP_STAGE1(kc + 2, (kc + 2) % 3);

        const uint32_t stage = sb + (kc % 3) * G1_STAGE;
#pragma unroll
        for (int ks = 0; ks < 2; ks++) {
            uint32_t Ah[2][4], Al[2][4], Bh[8][2], Bl[8][2];
#pragma unroll
            for (int mi = 0; mi < 2; mi++) {
                int row = wm + mi * 16 + a_mrow;
                int gran = ks * 2 + a_g;
                uint32_t addr = stage + row * 64 + ((gran ^ ((row >> 1) & 3)) << 4);
                ldsm_x4(Ah[mi], addr);
                ldsm_x4(Al[mi], addr + G1_AT);
            }
#pragma unroll
            for (int nb = 0; nb < 4; nb++) {
                int row = wn + nb * 16 + b_nrow;
                int gran = ks * 2 + b_g;
                uint32_t addr = stage + 2 * G1_AT + row * 64 +
                                ((gran ^ ((row >> 1) & 3)) << 4);
                uint32_t t[4];
                ldsm_x4(t, addr);
                Bh[nb * 2][0] = t[0]; Bh[nb * 2][1] = t[1];
                Bh[nb * 2 + 1][0] = t[2]; Bh[nb * 2 + 1][1] = t[3];
                ldsm_x4(t, addr + G1_BT);
                Bl[nb * 2][0] = t[0]; Bl[nb * 2][1] = t[1];
                Bl[nb * 2 + 1][0] = t[2]; Bl[nb * 2 + 1][1] = t[3];
            }
            if (ks == 1) BAR2_ARRIVE();
#pragma unroll
            for (int mi = 0; mi < 2; mi++)
#pragma unroll
                for (int ni = 0; ni < 8; ni++) mma_bf16(acc[mi][ni], Ah[mi], Bh[ni]);
#pragma unroll
            for (int mi = 0; mi < 2; mi++)
#pragma unroll
                for (int ni = 0; ni < 8; ni++) mma_bf16(acc[mi][ni], Ah[mi], Bl[ni]);
#pragma unroll
            for (int mi = 0; mi < 2; mi++)
#pragma unroll
                for (int ni = 0; ni < 8; ni++) mma_bf16(acc[mi][ni], Al[mi], Bh[ni]);
        }
    }

    const int erow = lid >> 2, ecol = 2 * (lid & 3);
#pragma unroll
    for (int mi = 0; mi < 2; mi++) {
#pragma unroll
        for (int ni = 0; ni < 8; ni++) {
            float* c0 = C + (size_t)(bm + wm + mi * 16 + erow) * N + bn + wn + ni * 8 + ecol;
            *(float2*)c0 = make_float2(acc[mi][ni][0], acc[mi][ni][1]);
            *(float2*)(c0 + 8 * N) = make_float2(acc[mi][ni][2], acc[mi][ni][3]);
        }
    }
}

// ---------------------------------------------------------------------------
// Pass A (tensor-core): chunk totals
// ---------------------------------------------------------------------------
#define CS_TILE (64 * P72 * 2)

__global__ __launch_bounds__(256) void chunk_sums_tc() {
    __shared__ char sm[4 * CS_TILE];
    const uint32_t sb = smem_u32(sm);
    __nv_bfloat16* Ah = (__nv_bfloat16*)sm;
    __nv_bfloat16* Al = (__nv_bfloat16*)(sm + CS_TILE);
    __nv_bfloat16* Bh = (__nv_bfloat16*)(sm + 2 * CS_TILE);
    __nv_bfloat16* Bl = (__nv_bfloat16*)(sm + 3 * CS_TILE);

    const int ck = blockIdx.x, bh = blockIdx.y;
    const int b = bh >> 4, h = bh & 15;
    const int tid = threadIdx.x;

    for (int i = tid; i < 4096; i += 256) {
        int tt = i >> 6, c = i & 63;
        const float* row = g_qkv + (size_t)(b * TT + ck * CHUNK + tt) * QKVW;
        __nv_bfloat16 hh, ll;
        float e = __expf(row[(NH + h) * HS + c]);
        split1(e, hh, ll);
        Ah[c * P72 + tt] = hh; Al[c * P72 + tt] = ll;
        float v = row[(2 * NH + h) * HS + c];
        split1(v, hh, ll);
        Bh[c * P72 + tt] = hh; Bl[c * P72 + tt] = ll;
    }
    __syncthreads();

    const int wid = tid >> 5, lid = tid & 31;
    const int a_mrow = (lid < 16 ? lid : lid - 16), a_g = (lid < 16 ? 0 : 1);
    const int b_q = lid & 7, b_g4 = lid >> 3;
    const int b_nrow = b_q + (b_g4 >> 1) * 8, b_g = b_g4 & 1;
    const int wm = (wid & 1) * 32, wn = (wid >> 1) * 16;

    float acc[2][2][4];
#pragma unroll
    for (int mi = 0; mi < 2; mi++)
#pragma unroll
        for (int ni = 0; ni < 2; ni++)
#pragma unroll
            for (int q = 0; q < 4; q++) acc[mi][ni][q] = 0.f;

    mm_tile<2, 1>(sb, sb + CS_TILE, sb + 2 * CS_TILE, sb + 3 * CS_TILE,
                  wm, wn, a_mrow, a_g, b_nrow, b_g, acc);

    float* st = g_state + (size_t)(bh * NCK + ck) * STSZ;
    const int erow = lid >> 2, ecol = 2 * (lid & 3);
#pragma unroll
    for (int mi = 0; mi < 2; mi++)
#pragma unroll
        for (int ni = 0; ni < 2; ni++) {
            int r = wm + mi * 16 + erow, cc = wn + ni * 8 + ecol;
            *(float2*)&st[r * 64 + cc] = make_float2(acc[mi][ni][0], acc[mi][ni][1]);
            *(float2*)&st[(r + 8) * 64 + cc] = make_float2(acc[mi][ni][2], acc[mi][ni][3]);
        }

    if (tid < 64) {
        float s = 0.f;
        for (int t2 = 0; t2 < 64; t2++)
            s += __bfloat162float(Ah[tid * P72 + t2]) + __bfloat162float(Al[tid * P72 + t2]);
        st[4096 + tid] = s;
    }
}

// ---------------------------------------------------------------------------
// Pass B: exclusive prefix over the 32 chunks
// ---------------------------------------------------------------------------
__global__ __launch_bounds__(256) void chunk_prefix() {
    const int bh = blockIdx.y;
    const int idx = blockIdx.x * 256 + threadIdx.x;
    if (idx >= STSZ) return;
    float run = 0.f;
    float* base = g_state + (size_t)bh * NCK * STSZ + idx;
    for (int ck = 0; ck < NCK; ck++) {
        float t = base[(size_t)ck * STSZ];
        base[(size_t)ck * STSZ] = run;
        run += t;
    }
}

// ---------------------------------------------------------------------------
// Pass C (tensor-core): intra-chunk attention. 72KB smem -> 3 CTAs/SM.
// ---------------------------------------------------------------------------
#define IC3_SMEM 73728

__global__ __launch_bounds__(256) void intra_tc() {
    extern __shared__ char sm[];
    float* Qf = (float*)sm;
    const uint32_t sb = smem_u32(sm);
    const uint32_t R2h = sb,          R2l = sb + 9216;
    const uint32_t R3h = sb + 18432,  R3l = sb + 27648;
    const uint32_t R4h = sb + 36864,  R4l = sb + 46080;
    const uint32_t R5h = sb + 55296,  R5l = sb + 64512;
    __nv_bfloat16* pR2h = (__nv_bfloat16*)(sm);
    __nv_bfloat16* pR2l = (__nv_bfloat16*)(sm + 9216);
    __nv_bfloat16* pR3h = (__nv_bfloat16*)(sm + 18432);
    __nv_bfloat16* pR3l = (__nv_bfloat16*)(sm + 27648);
    __nv_bfloat16* pR4h = (__nv_bfloat16*)(sm + 36864);
    __nv_bfloat16* pR4l = (__nv_bfloat16*)(sm + 46080);
    __nv_bfloat16* pR5h = (__nv_bfloat16*)(sm + 55296);
    __nv_bfloat16* pR5l = (__nv_bfloat16*)(sm + 64512);
    __shared__ float den0[64];

    const int ck = blockIdx.x, bh = blockIdx.y;
    const int b = bh >> 4, h = bh & 15;
    const int tid = threadIdx.x;
    const float* st = g_state + (size_t)(bh * NCK + ck) * STSZ;

    for (int i = tid; i < 4096; i += 256) {
        int tt = i >> 6, c = i & 63;
        const float* row = g_qkv + (size_t)(b * TT + ck * CHUNK + tt) * QKVW;
        Qf[tt * PAD + c] = row[h * HS + c];
        __nv_bfloat16 hh, ll;
        float e = __expf(row[(NH + h) * HS + c]);
        split1(e, hh, ll);
        pR3h[tt * P72 + c] = hh; pR3l[tt * P72 + c] = ll;
        float v = row[(2 * NH + h) * HS + c];
        split1(v, hh, ll);
        pR5h[c * P72 + tt] = hh; pR5l[c * P72 + tt] = ll;
        split1(st[i], hh, ll);
        pR4h[(i & 63) * P72 + (i >> 6)] = hh;
        pR4l[(i & 63) * P72 + (i >> 6)] = ll;
    }
    if (tid < 64) den0[tid] = st[4096 + tid];
    __syncthreads();

    {
        const int tq = tid >> 2, qd = tid & 3;
        float* qseg = Qf + tq * PAD + qd * 16;
        float v[16];
#pragma unroll
        for (int q = 0; q < 4; q++) {
            float4 f = ((const float4*)qseg)[q];
            v[4*q] = f.x; v[4*q+1] = f.y; v[4*q+2] = f.z; v[4*q+3] = f.w;
        }
        float m = v[0];
#pragma unroll
        for (int j = 1; j < 16; j++) m = fmaxf(m, v[j]);
        m = fmaxf(m, __shfl_xor_sync(0xFFFFFFFFu, m, 1));
        m = fmaxf(m, __shfl_xor_sync(0xFFFFFFFFu, m, 2));
        float s = 0.f;
#pragma unroll
        for (int j = 0; j < 16; j++) { v[j] = __expf(v[j] - m); s += v[j]; }
        s += __shfl_xor_sync(0xFFFFFFFFu, s, 1);
        s += __shfl_xor_sync(0xFFFFFFFFu, s, 2);
        float inv = 0.125f / s;
#pragma unroll
        for (int q = 0; q < 4; q++)
            ((float4*)qseg)[q] = make_float4(v[4*q] * inv, v[4*q+1] * inv,
                                             v[4*q+2] * inv, v[4*q+3] * inv);
    }
    __syncthreads();

    {
        const int c = tid >> 2, sg = tid & 3;
        float cum[16];
        float s = 0.f;
#pragma unroll
        for (int j = 0; j < 16; j++) {
            int t2 = sg * 16 + j;
            s += __bfloat162float(pR3h[t2 * P72 + c]) + __bfloat162float(pR3l[t2 * P72 + c]);
            cum[j] = s;
        }
        float x = s;
        float u1 = __shfl_up_sync(0xFFFFFFFFu, x, 1); if (sg >= 1) x += u1;
        float u2 = __shfl_up_sync(0xFFFFFFFFu, x, 2); if (sg >= 2) x += u2;
        float base = den0[c] + (x - s);
#pragma unroll
        for (int j = 0; j < 16; j++) {
            int t2 = sg * 16 + j;
            Qf[t2 * PAD + c] = Qf[t2 * PAD + c] / (base + cum[j] + 1e-9f);
        }
    }
    __syncthreads();

    {
        float qreg[16];
#pragma unroll
        for (int it = 0; it < 16; it++) {
            int i = tid + it * 256;
            qreg[it] = Qf[(i >> 6) * PAD + (i & 63)];
        }
        __syncthreads();
#pragma unroll
        for (int it = 0; it < 16; it++) {
            int i = tid + it * 256;
            __nv_bfloat16 hh, ll;
            split1(qreg[it], hh, ll);
            pR2h[(i >> 6) * P72 + (i & 63)] = hh;
            pR2l[(i >> 6) * P72 + (i & 63)] = ll;
        }
    }
    __syncthreads();

    const int wid = tid >> 5, lid = tid & 31;
    const int a_mrow = (lid < 16 ? lid : lid - 16), a_g = (lid < 16 ? 0 : 1);
    const int b_q = lid & 7, b_g4 = lid >> 3;
    const int b_nrow = b_q + (b_g4 >> 1) * 8, b_g = b_g4 & 1;
    const int erow = lid >> 2, ecol = 2 * (lid & 3);

    float accS[2][4][4], accA[2][4][4];
    if (wid < 4) {
#pragma unroll
        for (int mi = 0; mi < 2; mi++)
#pragma unroll
            for (int ni = 0; ni < 4; ni++)
#pragma unroll
                for (int q = 0; q < 4; q++) accS[mi][ni][q] = 0.f;
        int wm = (wid & 1) * 32, wn = (wid >> 1) * 32;
        mm_tile<2, 2>(R2h, R2l, R4h, R4l, wm, wn, a_mrow, a_g, b_nrow, b_g, accS);
    } else {
#pragma unroll
        for (int mi = 0; mi < 2; mi++)
#pragma unroll
            for (int ni = 0; ni < 4; ni++)
#pragma unroll
                for (int q = 0; q < 4; q++) accA[mi][ni][q] = 0.f;
        int w4 = wid - 4;
        int wm = (w4 & 1) * 32, wn = (w4 >> 1) * 32;
        mm_tile<2, 2>(R2h, R2l, R3h, R3l, wm, wn, a_mrow, a_g, b_nrow, b_g, accA);
    }
    __syncthreads();

    if (wid < 4) {
        int wm = (wid & 1) * 32, wn = (wid >> 1) * 32;
#pragma unroll
        for (int mi = 0; mi < 2; mi++)
#pragma unroll
            for (int ni = 0; ni < 4; ni++) {
                int r = wm + mi * 16 + erow, d = wn + ni * 8 + ecol;
                *(float2*)&Qf[r * PAD + d] = make_float2(accS[mi][ni][0], accS[mi][ni][1]);
                *(float2*)&Qf[(r + 8) * PAD + d] = make_float2(accS[mi][ni][2], accS[mi][ni][3]);
            }
    } else {
        int w4 = wid - 4;
        int wm = (w4 & 1) * 32, wn = (w4 >> 1) * 32;
#pragma unroll
        for (int mi = 0; mi < 2; mi++)
#pragma unroll
            for (int ni = 0; ni < 4; ni++) {
                int r0 = wm + mi * 16 + erow, s0 = wn + ni * 8 + ecol;
                float v0 = (s0 <= r0) ? accA[mi][ni][0] : 0.f;
                float v1 = (s0 + 1 <= r0) ? accA[mi][ni][1] : 0.f;
                uint32_t hp, lp;
                split2(v0, v1, hp, lp);
                *(uint32_t*)&pR4h[r0 * P72 + s0] = hp;
                *(uint32_t*)&pR4l[r0 * P72 + s0] = lp;
                int r2 = r0 + 8;
                float v2 = (s0 <= r2) ? accA[mi][ni][2] : 0.f;
                float v3 = (s0 + 1 <= r2) ? accA[mi][ni][3] : 0.f;
                split2(v2, v3, hp, lp);
                *(uint32_t*)&pR4h[r2 * P72 + s0] = hp;
                *(uint32_t*)&pR4l[r2 * P72 + s0] = lp;
            }
    }
    __syncthreads();

    {
        float accV[1][4][4];
#pragma unroll
        for (int ni = 0; ni < 4; ni++)
#pragma unroll
            for (int q = 0; q < 4; q++) accV[0][ni][q] = 0.f;
        int wm = (wid & 3) * 16, wn = (wid >> 2) * 32;
        mm_tile<1, 2>(R4h, R4l, R5h, R5l, wm, wn, a_mrow, a_g, b_nrow, b_g, accV);
#pragma unroll
        for (int ni = 0; ni < 4; ni++) {
            int r = wm + erow, d = wn + ni * 8 + ecol;
            uint32_t hp, lp;
            float x0 = accV[0][ni][0] + Qf[r * PAD + d];
            float x1 = accV[0][ni][1] + Qf[r * PAD + d + 1];
            split2(x0, x1, hp, lp);
            size_t g0 = (size_t)(b * TT + ck * CHUNK + r) * DM + h * HS + d;
            *(uint32_t*)&g_xoh[g0] = hp;
            *(uint32_t*)&g_xol[g0] = lp;
            int r2 = r + 8;
            float x2 = accV[0][ni][2] + Qf[r2 * PAD + d];
            float x3 = accV[0][ni][3] + Qf[r2 * PAD + d + 1];
            split2(x2, x3, hp, lp);
            size_t g2 = (size_t)(b * TT + ck * CHUNK + r2) * DM + h * HS + d;
            *(uint32_t*)&g_xoh[g2] = hp;
            *(uint32_t*)&g_xol[g2] = lp;
        }
    }
}

// ---------------------------------------------------------------------------
extern "C" void kernel_launch(void* const* d_in, const int* in_sizes, int n_in,
                              void* d_out, int out_size) {
    const float* x    = (const float*)d_in[0];
    const float* Wqkv = (const float*)d_in[1];
    const float* Wout = (const float*)d_in[2];
    float* out = (float*)d_out;

    float* qkv;
    cudaGetSymbolAddress((void**)&qkv, g_qkv);
    __nv_bfloat16 *xhi, *xlo, *wqh, *wql, *woh, *wol, *xoh, *xol;
    cudaGetSymbolAddress((void**)&xhi, g_xhi);
    cudaGetSymbolAddress((void**)&xlo, g_xlo);
    cudaGetSymbolAddress((void**)&wqh, g_wqh);
    cudaGetSymbolAddress((void**)&wql, g_wql);
    cudaGetSymbolAddress((void**)&woh, g_woh);
    cudaGetSymbolAddress((void**)&wol, g_wol);
    cudaGetSymbolAddress((void**)&xoh, g_xoh);
    cudaGetSymbolAddress((void**)&xol, g_xol);

    cudaFuncSetAttribute(gemm_bf16, cudaFuncAttributeMaxDynamicSharedMemorySize, GEMM_SMEM_B);
    cudaFuncSetAttribute(gemm_bf16_64, cudaFuncAttributeMaxDynamicSharedMemorySize, G1_SMEM);
    cudaFuncSetAttribute(intra_tc, cudaFuncAttributeMaxDynamicSharedMemorySize, IC3_SMEM);

    // 0) split inputs
    split_f32<<<(BB * TT * DM) / 1024, 256>>>(x, xhi, xlo, BB * TT * DM);
    split_f32<<<(QKVW * DM) / 1024, 256>>>(Wqkv, wqh, wql, QKVW * DM);
    split_f32<<<(DM * DM) / 1024, 256>>>(Wout, woh, wol, DM * DM);

    // 1) qkv = x @ Wqkv^T : 64x128 tiles, 3 CTAs/SM (best measured: 196.6us @70%)
    gemm_bf16_64<<<dim3(QKVW / 128, (BB * TT) / 64), 128, G1_SMEM>>>(
        xhi, xlo, wqh, wql, qkv, BB * TT, QKVW, DM);
    // 2) chunk totals
    chunk_sums_tc<<<dim3(NCK, NBH), 256>>>();
    // 3) exclusive prefix
    chunk_prefix<<<dim3((STSZ + 255) / 256, NBH), 256>>>();
    // 4) intra-chunk attention (3 CTAs/SM)
    intra_tc<<<dim3(NCK, NBH), 256, IC3_SMEM>>>();
    // 5) out = xo @ Wout^T : 128x128 tiles -> 256 CTAs = 1 clean wave
    gemm_bf16<<<dim3(DM / 128, (BB * TT) / 128), 256, GEMM_SMEM_B>>>(
        xoh, xol, woh, wol, out, BB * TT, DM, DM);
}

// round 17
// speedup vs baseline: 1.0016x; 1.0016x over previous
#include <cuda_runtime.h>
#include <cuda_bf16.h>
#include <cstdint>

// Problem constants
#define BB 2
#define TT 2048
#define DM 1024
#define NH 16
#define HS 64
#define QKVW 3072
#define CHUNK 64
#define NCK (TT / CHUNK)
#define NBH (BB * NH)
#define STSZ (HS * HS + HS)
#define PAD 68
#define P72 72

// Scratch
__device__ float g_qkv[(size_t)BB * TT * QKVW];
__device__ float g_state[(size_t)NBH * NCK * STSZ];
__device__ __nv_bfloat16 g_xhi[(size_t)BB * TT * DM];
__device__ __nv_bfloat16 g_xlo[(size_t)BB * TT * DM];
__device__ __nv_bfloat16 g_wqh[(size_t)QKVW * DM];
__device__ __nv_bfloat16 g_wql[(size_t)QKVW * DM];
__device__ __nv_bfloat16 g_woh[(size_t)DM * DM];
__device__ __nv_bfloat16 g_wol[(size_t)DM * DM];
__device__ __nv_bfloat16 g_xoh[(size_t)BB * TT * DM];
__device__ __nv_bfloat16 g_xol[(size_t)BB * TT * DM];

// ===========================================================================
// Helpers
// ===========================================================================
__device__ __forceinline__ uint32_t smem_u32(const void* p) {
    uint32_t a;
    asm("{ .reg .u64 t; cvta.to.shared.u64 t, %1; cvt.u32.u64 %0, t; }"
        : "=r"(a) : "l"(p));
    return a;
}

#define CP_ASYNC16(dst, src) \
    asm volatile("cp.async.cg.shared.global [%0], [%1], 16;" :: "r"(dst), "l"(src))
#define CP_COMMIT() asm volatile("cp.async.commit_group;" ::: "memory")
#define CP_WAIT1()  asm volatile("cp.async.wait_group 1;" ::: "memory")
#define CP_WAIT0()  asm volatile("cp.async.wait_group 0;" ::: "memory")

// 128-thread split barrier
#define BAR2_ARRIVE() asm volatile("bar.arrive 1, 256;" ::: "memory")
#define BAR2_SYNC()   asm volatile("bar.sync 1, 256;" ::: "memory")

__device__ __forceinline__ void ldsm_x4(uint32_t* r, uint32_t addr) {
    asm volatile("ldmatrix.sync.aligned.m8n8.x4.shared.b16 {%0,%1,%2,%3}, [%4];"
                 : "=r"(r[0]), "=r"(r[1]), "=r"(r[2]), "=r"(r[3]) : "r"(addr));
}

__device__ __forceinline__ void mma_bf16(float* c, const uint32_t* a, const uint32_t* b) {
    asm volatile(
        "mma.sync.aligned.m16n8k16.row.col.f32.bf16.bf16.f32 "
        "{%0,%1,%2,%3}, {%4,%5,%6,%7}, {%8,%9}, {%0,%1,%2,%3};"
        : "+f"(c[0]), "+f"(c[1]), "+f"(c[2]), "+f"(c[3])
        : "r"(a[0]), "r"(a[1]), "r"(a[2]), "r"(a[3]), "r"(b[0]), "r"(b[1]));
}

__device__ __forceinline__ void split2(float a, float b, uint32_t& hp, uint32_t& lp) {
    __nv_bfloat162 h = __floats2bfloat162_rn(a, b);
    float2 hf = __bfloat1622float2(h);
    __nv_bfloat162 l = __floats2bfloat162_rn(a - hf.x, b - hf.y);
    hp = *(uint32_t*)&h;
    lp = *(uint32_t*)&l;
}

__device__ __forceinline__ void split1(float v, __nv_bfloat16& h, __nv_bfloat16& l) {
    h = __float2bfloat16(v);
    l = __float2bfloat16(v - __bfloat162float(h));
}

// Generic split-bf16 MMA tile (pitch-72 bf16 smem, NT, K=64). Term-major.
template<int MI, int NB>
__device__ __forceinline__ void mm_tile(uint32_t Ahb, uint32_t Alb,
                                        uint32_t Bhb, uint32_t Blb,
                                        int wm, int wn,
                                        int a_mrow, int a_g, int b_nrow, int b_g,
                                        float acc[MI][2 * NB][4]) {
#pragma unroll
    for (int ks = 0; ks < 4; ks++) {
        uint32_t Ah[MI][4], Al[MI][4], Bh[2 * NB][2], Bl[2 * NB][2];
#pragma unroll
        for (int mi = 0; mi < MI; mi++) {
            uint32_t ao = (uint32_t)((wm + mi * 16 + a_mrow) * (P72 * 2) + (ks * 2 + a_g) * 16);
            ldsm_x4(Ah[mi], Ahb + ao);
            ldsm_x4(Al[mi], Alb + ao);
        }
#pragma unroll
        for (int nb = 0; nb < NB; nb++) {
            uint32_t bo = (uint32_t)((wn + nb * 16 + b_nrow) * (P72 * 2) + (ks * 2 + b_g) * 16);
            uint32_t t0[4], t1[4];
            ldsm_x4(t0, Bhb + bo);
            ldsm_x4(t1, Blb + bo);
            Bh[nb * 2][0] = t0[0]; Bh[nb * 2][1] = t0[1];
            Bh[nb * 2 + 1][0] = t0[2]; Bh[nb * 2 + 1][1] = t0[3];
            Bl[nb * 2][0] = t1[0]; Bl[nb * 2][1] = t1[1];
            Bl[nb * 2 + 1][0] = t1[2]; Bl[nb * 2 + 1][1] = t1[3];
        }
#pragma unroll
        for (int mi = 0; mi < MI; mi++)
#pragma unroll
            for (int ni = 0; ni < 2 * NB; ni++) mma_bf16(acc[mi][ni], Ah[mi], Bh[ni]);
#pragma unroll
        for (int mi = 0; mi < MI; mi++)
#pragma unroll
            for (int ni = 0; ni < 2 * NB; ni++) mma_bf16(acc[mi][ni], Ah[mi], Bl[ni]);
#pragma unroll
        for (int mi = 0; mi < MI; mi++)
#pragma unroll
            for (int ni = 0; ni < 2 * NB; ni++) mma_bf16(acc[mi][ni], Al[mi], Bh[ni]);
    }
}

// ---------------------------------------------------------------------------
// Prep: fp32 -> bf16 hi/lo split
// ---------------------------------------------------------------------------
__global__ __launch_bounds__(256) void split_f32(const float* __restrict__ src,
                                                 __nv_bfloat16* __restrict__ hi,
                                                 __nv_bfloat16* __restrict__ lo,
                                                 int n) {
    int i = (blockIdx.x * 256 + threadIdx.x) * 4;
    if (i >= n) return;
    float4 v = *(const float4*)(src + i);
    uint32_t h0, l0, h1, l1;
    split2(v.x, v.y, h0, l0);
    split2(v.z, v.w, h1, l1);
    *(uint2*)(hi + i) = make_uint2(h0, h1);
    *(uint2*)(lo + i) = make_uint2(l0, l1);
}

#define KT 32

// ===========================================================================
// GEMM: 64x128 tile, 128 threads, warp grid 2x2 (32x64/warp), NSTAGE=3,
// 3 CTAs/SM. Used for BOTH gemm1 and gemm2 (R12 config, measured 388.6us).
// Stage layout: Ahi(4KB) Alo(4KB) Bhi(8KB) Blo(8KB) = 24576 B.
// ===========================================================================
#define G1_AT 4096
#define G1_BT 8192
#define G1_STAGE 24576
#define G1_SMEM (3 * G1_STAGE)   // 73728 B

__global__ __launch_bounds__(128, 3) void gemm_bf16_64(
        const __nv_bfloat16* __restrict__ Ahi,
        const __nv_bfloat16* __restrict__ Alo,
        const __nv_bfloat16* __restrict__ Bhi,
        const __nv_bfloat16* __restrict__ Blo,
        float* __restrict__ C,
        int M, int N, int K) {
    extern __shared__ char smraw[];
    const uint32_t sb = smem_u32(smraw);
    const int tid = threadIdx.x, wid = tid >> 5, lid = tid & 31;
    const int bm = blockIdx.y * 64, bn = blockIdx.x * 128;
    const int wm = (wid & 1) * 32, wn = (wid >> 1) * 64;
    const int NC = K / KT;

#define CP_STAGE1(kc, s)                                                       \
    {                                                                          \
        uint32_t stb = sb + (s) * G1_STAGE;                                    \
        _Pragma("unroll")                                                      \
        for (int it = 0; it < 4; it++) {  /* A: 512 granules */                \
            int cid = it * 128 + tid;                                          \
            int comp = cid >> 8;                                               \
            int rem = cid & 255;                                               \
            int r = rem >> 2, g = rem & 3;                                     \
            const __nv_bfloat16* src = (comp ? Alo : Ahi) +                    \
                (size_t)(bm + r) * K + (kc) * KT + g * 8;                      \
            uint32_t dst = stb + comp * G1_AT + r * 64 +                       \
                           ((g ^ ((r >> 1) & 3)) << 4);                        \
            CP_ASYNC16(dst, src);                                              \
        }                                                                      \
        _Pragma("unroll")                                                      \
        for (int it = 0; it < 8; it++) {  /* B: 1024 granules */               \
            int cid = it * 128 + tid;                                          \
            int comp = cid >> 9;                                               \
            int rem = cid & 511;                                               \
            int r = rem >> 2, g = rem & 3;                                     \
            const __nv_bfloat16* src = (comp ? Blo : Bhi) +                    \
                (size_t)(bn + r) * K + (kc) * KT + g * 8;                      \
            uint32_t dst = stb + 2 * G1_AT + comp * G1_BT + r * 64 +           \
                           ((g ^ ((r >> 1) & 3)) << 4);                        \
            CP_ASYNC16(dst, src);                                              \
        }                                                                      \
        CP_COMMIT();                                                           \
    }

    float acc[2][8][4];
#pragma unroll
    for (int mi = 0; mi < 2; mi++)
#pragma unroll
        for (int ni = 0; ni < 8; ni++)
#pragma unroll
            for (int q = 0; q < 4; q++) acc[mi][ni][q] = 0.f;

    const int a_mrow = (lid < 16 ? lid : lid - 16);
    const int a_g    = (lid < 16 ? 0 : 1);
    const int b_q = lid & 7, b_g4 = lid >> 3;
    const int b_nrow = b_q + (b_g4 >> 1) * 8;
    const int b_g    = (b_g4 & 1);

    CP_STAGE1(0, 0);
    CP_STAGE1(1, 1);
    BAR2_ARRIVE();

    for (int kc = 0; kc < NC; kc++) {
        if (kc < NC - 1) { CP_WAIT1(); } else { CP_WAIT0(); }
        BAR2_SYNC();
        if (kc + 2 < NC) CP_STAGE1(kc + 2, (kc + 2) % 3);

        const uint32_t stage = sb + (kc % 3) * G1_STAGE;
#pragma unroll
        for (int ks = 0; ks < 2; ks++) {
            uint32_t Ah[2][4], Al[2][4], Bh[8][2], Bl[8][2];
#pragma unroll
            for (int mi = 0; mi < 2; mi++) {
                int row = wm + mi * 16 + a_mrow;
                int gran = ks * 2 + a_g;
                uint32_t addr = stage + row * 64 + ((gran ^ ((row >> 1) & 3)) << 4);
                ldsm_x4(Ah[mi], addr);
                ldsm_x4(Al[mi], addr + G1_AT);
            }
#pragma unroll
            for (int nb = 0; nb < 4; nb++) {
                int row = wn + nb * 16 + b_nrow;
                int gran = ks * 2 + b_g;
                uint32_t addr = stage + 2 * G1_AT + row * 64 +
                                ((gran ^ ((row >> 1) & 3)) << 4);
                uint32_t t[4];
                ldsm_x4(t, addr);
                Bh[nb * 2][0] = t[0]; Bh[nb * 2][1] = t[1];
                Bh[nb * 2 + 1][0] = t[2]; Bh[nb * 2 + 1][1] = t[3];
                ldsm_x4(t, addr + G1_BT);
                Bl[nb * 2][0] = t[0]; Bl[nb * 2][1] = t[1];
                Bl[nb * 2 + 1][0] = t[2]; Bl[nb * 2 + 1][1] = t[3];
            }
            if (ks == 1) BAR2_ARRIVE();
#pragma unroll
            for (int mi = 0; mi < 2; mi++)
#pragma unroll
                for (int ni = 0; ni < 8; ni++) mma_bf16(acc[mi][ni], Ah[mi], Bh[ni]);
#pragma unroll
            for (int mi = 0; mi < 2; mi++)
#pragma unroll
                for (int ni = 0; ni < 8; ni++) mma_bf16(acc[mi][ni], Ah[mi], Bl[ni]);
#pragma unroll
            for (int mi = 0; mi < 2; mi++)
#pragma unroll
                for (int ni = 0; ni < 8; ni++) mma_bf16(acc[mi][ni], Al[mi], Bh[ni]);
        }
    }

    const int erow = lid >> 2, ecol = 2 * (lid & 3);
#pragma unroll
    for (int mi = 0; mi < 2; mi++) {
#pragma unroll
        for (int ni = 0; ni < 8; ni++) {
            float* c0 = C + (size_t)(bm + wm + mi * 16 + erow) * N + bn + wn + ni * 8 + ecol;
            *(float2*)c0 = make_float2(acc[mi][ni][0], acc[mi][ni][1]);
            *(float2*)(c0 + 8 * N) = make_float2(acc[mi][ni][2], acc[mi][ni][3]);
        }
    }
}

// ---------------------------------------------------------------------------
// Pass A (tensor-core): chunk totals
// ---------------------------------------------------------------------------
#define CS_TILE (64 * P72 * 2)

__global__ __launch_bounds__(256) void chunk_sums_tc() {
    __shared__ char sm[4 * CS_TILE];
    const uint32_t sb = smem_u32(sm);
    __nv_bfloat16* Ah = (__nv_bfloat16*)sm;
    __nv_bfloat16* Al = (__nv_bfloat16*)(sm + CS_TILE);
    __nv_bfloat16* Bh = (__nv_bfloat16*)(sm + 2 * CS_TILE);
    __nv_bfloat16* Bl = (__nv_bfloat16*)(sm + 3 * CS_TILE);

    const int ck = blockIdx.x, bh = blockIdx.y;
    const int b = bh >> 4, h = bh & 15;
    const int tid = threadIdx.x;

    for (int i = tid; i < 4096; i += 256) {
        int tt = i >> 6, c = i & 63;
        const float* row = g_qkv + (size_t)(b * TT + ck * CHUNK + tt) * QKVW;
        __nv_bfloat16 hh, ll;
        float e = __expf(row[(NH + h) * HS + c]);
        split1(e, hh, ll);
        Ah[c * P72 + tt] = hh; Al[c * P72 + tt] = ll;
        float v = row[(2 * NH + h) * HS + c];
        split1(v, hh, ll);
        Bh[c * P72 + tt] = hh; Bl[c * P72 + tt] = ll;
    }
    __syncthreads();

    const int wid = tid >> 5, lid = tid & 31;
    const int a_mrow = (lid < 16 ? lid : lid - 16), a_g = (lid < 16 ? 0 : 1);
    const int b_q = lid & 7, b_g4 = lid >> 3;
    const int b_nrow = b_q + (b_g4 >> 1) * 8, b_g = b_g4 & 1;
    const int wm = (wid & 1) * 32, wn = (wid >> 1) * 16;

    float acc[2][2][4];
#pragma unroll
    for (int mi = 0; mi < 2; mi++)
#pragma unroll
        for (int ni = 0; ni < 2; ni++)
#pragma unroll
            for (int q = 0; q < 4; q++) acc[mi][ni][q] = 0.f;

    mm_tile<2, 1>(sb, sb + CS_TILE, sb + 2 * CS_TILE, sb + 3 * CS_TILE,
                  wm, wn, a_mrow, a_g, b_nrow, b_g, acc);

    float* st = g_state + (size_t)(bh * NCK + ck) * STSZ;
    const int erow = lid >> 2, ecol = 2 * (lid & 3);
#pragma unroll
    for (int mi = 0; mi < 2; mi++)
#pragma unroll
        for (int ni = 0; ni < 2; ni++) {
            int r = wm + mi * 16 + erow, cc = wn + ni * 8 + ecol;
            *(float2*)&st[r * 64 + cc] = make_float2(acc[mi][ni][0], acc[mi][ni][1]);
            *(float2*)&st[(r + 8) * 64 + cc] = make_float2(acc[mi][ni][2], acc[mi][ni][3]);
        }

    if (tid < 64) {
        float s = 0.f;
        for (int t2 = 0; t2 < 64; t2++)
            s += __bfloat162float(Ah[tid * P72 + t2]) + __bfloat162float(Al[tid * P72 + t2]);
        st[4096 + tid] = s;
    }
}

// ---------------------------------------------------------------------------
// Pass B: exclusive prefix over the 32 chunks
// ---------------------------------------------------------------------------
__global__ __launch_bounds__(256) void chunk_prefix() {
    const int bh = blockIdx.y;
    const int idx = blockIdx.x * 256 + threadIdx.x;
    if (idx >= STSZ) return;
    float run = 0.f;
    float* base = g_state + (size_t)bh * NCK * STSZ + idx;
    for (int ck = 0; ck < NCK; ck++) {
        float t = base[(size_t)ck * STSZ];
        base[(size_t)ck * STSZ] = run;
        run += t;
    }
}

// ---------------------------------------------------------------------------
// Pass C (tensor-core): intra-chunk attention. 72KB smem -> 3 CTAs/SM.
// ---------------------------------------------------------------------------
#define IC3_SMEM 73728

__global__ __launch_bounds__(256) void intra_tc() {
    extern __shared__ char sm[];
    float* Qf = (float*)sm;
    const uint32_t sb = smem_u32(sm);
    const uint32_t R2h = sb,          R2l = sb + 9216;
    const uint32_t R3h = sb + 18432,  R3l = sb + 27648;
    const uint32_t R4h = sb + 36864,  R4l = sb + 46080;
    const uint32_t R5h = sb + 55296,  R5l = sb + 64512;
    __nv_bfloat16* pR2h = (__nv_bfloat16*)(sm);
    __nv_bfloat16* pR2l = (__nv_bfloat16*)(sm + 9216);
    __nv_bfloat16* pR3h = (__nv_bfloat16*)(sm + 18432);
    __nv_bfloat16* pR3l = (__nv_bfloat16*)(sm + 27648);
    __nv_bfloat16* pR4h = (__nv_bfloat16*)(sm + 36864);
    __nv_bfloat16* pR4l = (__nv_bfloat16*)(sm + 46080);
    __nv_bfloat16* pR5h = (__nv_bfloat16*)(sm + 55296);
    __nv_bfloat16* pR5l = (__nv_bfloat16*)(sm + 64512);
    __shared__ float den0[64];

    const int ck = blockIdx.x, bh = blockIdx.y;
    const int b = bh >> 4, h = bh & 15;
    const int tid = threadIdx.x;
    const float* st = g_state + (size_t)(bh * NCK + ck) * STSZ;

    for (int i = tid; i < 4096; i += 256) {
        int tt = i >> 6, c = i & 63;
        const float* row = g_qkv + (size_t)(b * TT + ck * CHUNK + tt) * QKVW;
        Qf[tt * PAD + c] = row[h * HS + c];
        __nv_bfloat16 hh, ll;
        float e = __expf(row[(NH + h) * HS + c]);
        split1(e, hh, ll);
        pR3h[tt * P72 + c] = hh; pR3l[tt * P72 + c] = ll;
        float v = row[(2 * NH + h) * HS + c];
        split1(v, hh, ll);
        pR5h[c * P72 + tt] = hh; pR5l[c * P72 + tt] = ll;
        split1(st[i], hh, ll);
        pR4h[(i & 63) * P72 + (i >> 6)] = hh;
        pR4l[(i & 63) * P72 + (i >> 6)] = ll;
    }
    if (tid < 64) den0[tid] = st[4096 + tid];
    __syncthreads();

    {
        const int tq = tid >> 2, qd = tid & 3;
        float* qseg = Qf + tq * PAD + qd * 16;
        float v[16];
#pragma unroll
        for (int q = 0; q < 4; q++) {
            float4 f = ((const float4*)qseg)[q];
            v[4*q] = f.x; v[4*q+1] = f.y; v[4*q+2] = f.z; v[4*q+3] = f.w;
        }
        float m = v[0];
#pragma unroll
        for (int j = 1; j < 16; j++) m = fmaxf(m, v[j]);
        m = fmaxf(m, __shfl_xor_sync(0xFFFFFFFFu, m, 1));
        m = fmaxf(m, __shfl_xor_sync(0xFFFFFFFFu, m, 2));
        float s = 0.f;
#pragma unroll
        for (int j = 0; j < 16; j++) { v[j] = __expf(v[j] - m); s += v[j]; }
        s += __shfl_xor_sync(0xFFFFFFFFu, s, 1);
        s += __shfl_xor_sync(0xFFFFFFFFu, s, 2);
        float inv = 0.125f / s;
#pragma unroll
        for (int q = 0; q < 4; q++)
            ((float4*)qseg)[q] = make_float4(v[4*q] * inv, v[4*q+1] * inv,
                                             v[4*q+2] * inv, v[4*q+3] * inv);
    }
    __syncthreads();

    {
        const int c = tid >> 2, sg = tid & 3;
        float cum[16];
        float s = 0.f;
#pragma unroll
        for (int j = 0; j < 16; j++) {
            int t2 = sg * 16 + j;
            s += __bfloat162float(pR3h[t2 * P72 + c]) + __bfloat162float(pR3l[t2 * P72 + c]);
            cum[j] = s;
        }
        float x = s;
        float u1 = __shfl_up_sync(0xFFFFFFFFu, x, 1); if (sg >= 1) x += u1;
        float u2 = __shfl_up_sync(0xFFFFFFFFu, x, 2); if (sg >= 2) x += u2;
        float base = den0[c] + (x - s);
#pragma unroll
        for (int j = 0; j < 16; j++) {
            int t2 = sg * 16 + j;
            Qf[t2 * PAD + c] = Qf[t2 * PAD + c] / (base + cum[j] + 1e-9f);
        }
    }
    __syncthreads();

    {
        float qreg[16];
#pragma unroll
        for (int it = 0; it < 16; it++) {
            int i = tid + it * 256;
            qreg[it] = Qf[(i >> 6) * PAD + (i & 63)];
        }
        __syncthreads();
#pragma unroll
        for (int it = 0; it < 16; it++) {
            int i = tid + it * 256;
            __nv_bfloat16 hh, ll;
            split1(qreg[it], hh, ll);
            pR2h[(i >> 6) * P72 + (i & 63)] = hh;
            pR2l[(i >> 6) * P72 + (i & 63)] = ll;
        }
    }
    __syncthreads();

    const int wid = tid >> 5, lid = tid & 31;
    const int a_mrow = (lid < 16 ? lid : lid - 16), a_g = (lid < 16 ? 0 : 1);
    const int b_q = lid & 7, b_g4 = lid >> 3;
    const int b_nrow = b_q + (b_g4 >> 1) * 8, b_g = b_g4 & 1;
    const int erow = lid >> 2, ecol = 2 * (lid & 3);

    float accS[2][4][4], accA[2][4][4];
    if (wid < 4) {
#pragma unroll
        for (int mi = 0; mi < 2; mi++)
#pragma unroll
            for (int ni = 0; ni < 4; ni++)
#pragma unroll
                for (int q = 0; q < 4; q++) accS[mi][ni][q] = 0.f;
        int wm = (wid & 1) * 32, wn = (wid >> 1) * 32;
        mm_tile<2, 2>(R2h, R2l, R4h, R4l, wm, wn, a_mrow, a_g, b_nrow, b_g, accS);
    } else {
#pragma unroll
        for (int mi = 0; mi < 2; mi++)
#pragma unroll
            for (int ni = 0; ni < 4; ni++)
#pragma unroll
                for (int q = 0; q < 4; q++) accA[mi][ni][q] = 0.f;
        int w4 = wid - 4;
        int wm = (w4 & 1) * 32, wn = (w4 >> 1) * 32;
        mm_tile<2, 2>(R2h, R2l, R3h, R3l, wm, wn, a_mrow, a_g, b_nrow, b_g, accA);
    }
    __syncthreads();

    if (wid < 4) {
        int wm = (wid & 1) * 32, wn = (wid >> 1) * 32;
#pragma unroll
        for (int mi = 0; mi < 2; mi++)
#pragma unroll
            for (int ni = 0; ni < 4; ni++) {
                int r = wm + mi * 16 + erow, d = wn + ni * 8 + ecol;
                *(float2*)&Qf[r * PAD + d] = make_float2(accS[mi][ni][0], accS[mi][ni][1]);
                *(float2*)&Qf[(r + 8) * PAD + d] = make_float2(accS[mi][ni][2], accS[mi][ni][3]);
            }
    } else {
        int w4 = wid - 4;
        int wm = (w4 & 1) * 32, wn = (w4 >> 1) * 32;
#pragma unroll
        for (int mi = 0; mi < 2; mi++)
#pragma unroll
            for (int ni = 0; ni < 4; ni++) {
                int r0 = wm + mi * 16 + erow, s0 = wn + ni * 8 + ecol;
                float v0 = (s0 <= r0) ? accA[mi][ni][0] : 0.f;
                float v1 = (s0 + 1 <= r0) ? accA[mi][ni][1] : 0.f;
                uint32_t hp, lp;
                split2(v0, v1, hp, lp);
                *(uint32_t*)&pR4h[r0 * P72 + s0] = hp;
                *(uint32_t*)&pR4l[r0 * P72 + s0] = lp;
                int r2 = r0 + 8;
                float v2 = (s0 <= r2) ? accA[mi][ni][2] : 0.f;
                float v3 = (s0 + 1 <= r2) ? accA[mi][ni][3] : 0.f;
                split2(v2, v3, hp, lp);
                *(uint32_t*)&pR4h[r2 * P72 + s0] = hp;
                *(uint32_t*)&pR4l[r2 * P72 + s0] = lp;
            }
    }
    __syncthreads();

    {
        float accV[1][4][4];
#pragma unroll
        for (int ni = 0; ni < 4; ni++)
#pragma unroll
            for (int q = 0; q < 4; q++) accV[0][ni][q] = 0.f;
        int wm = (wid & 3) * 16, wn = (wid >> 2) * 32;
        mm_tile<1, 2>(R4h, R4l, R5h, R5l, wm, wn, a_mrow, a_g, b_nrow, b_g, accV);
#pragma unroll
        for (int ni = 0; ni < 4; ni++) {
            int r = wm + erow, d = wn + ni * 8 + ecol;
            uint32_t hp, lp;
            float x0 = accV[0][ni][0] + Qf[r * PAD + d];
            float x1 = accV[0][ni][1] + Qf[r * PAD + d + 1];
            split2(x0, x1, hp, lp);
            size_t g0 = (size_t)(b * TT + ck * CHUNK + r) * DM + h * HS + d;
            *(uint32_t*)&g_xoh[g0] = hp;
            *(uint32_t*)&g_xol[g0] = lp;
            int r2 = r + 8;
            float x2 = accV[0][ni][2] + Qf[r2 * PAD + d];
            float x3 = accV[0][ni][3] + Qf[r2 * PAD + d + 1];
            split2(x2, x3, hp, lp);
            size_t g2 = (size_t)(b * TT + ck * CHUNK + r2) * DM + h * HS + d;
            *(uint32_t*)&g_xoh[g2] = hp;
            *(uint32_t*)&g_xol[g2] = lp;
        }
    }
}

// ---------------------------------------------------------------------------
extern "C" void kernel_launch(void* const* d_in, const int* in_sizes, int n_in,
                              void* d_out, int out_size) {
    const float* x    = (const float*)d_in[0];
    const float* Wqkv = (const float*)d_in[1];
    const float* Wout = (const float*)d_in[2];
    float* out = (float*)d_out;

    float* qkv;
    cudaGetSymbolAddress((void**)&qkv, g_qkv);
    __nv_bfloat16 *xhi, *xlo, *wqh, *wql, *woh, *wol, *xoh, *xol;
    cudaGetSymbolAddress((void**)&xhi, g_xhi);
    cudaGetSymbolAddress((void**)&xlo, g_xlo);
    cudaGetSymbolAddress((void**)&wqh, g_wqh);
    cudaGetSymbolAddress((void**)&wql, g_wql);
    cudaGetSymbolAddress((void**)&woh, g_woh);
    cudaGetSymbolAddress((void**)&wol, g_wol);
    cudaGetSymbolAddress((void**)&xoh, g_xoh);
    cudaGetSymbolAddress((void**)&xol, g_xol);

    cudaFuncSetAttribute(gemm_bf16_64, cudaFuncAttributeMaxDynamicSharedMemorySize, G1_SMEM);
    cudaFuncSetAttribute(intra_tc, cudaFuncAttributeMaxDynamicSharedMemorySize, IC3_SMEM);

    // 0) split inputs into bf16 hi/lo
    split_f32<<<(BB * TT * DM) / 1024, 256>>>(x, xhi, xlo, BB * TT * DM);
    split_f32<<<(QKVW * DM) / 1024, 256>>>(Wqkv, wqh, wql, QKVW * DM);
    split_f32<<<(DM * DM) / 1024, 256>>>(Wout, woh, wol, DM * DM);

    // 1) qkv = x @ Wqkv^T : 64x128 tiles, 3 CTAs/SM
    gemm_bf16_64<<<dim3(QKVW / 128, (BB * TT) / 64), 128, G1_SMEM>>>(
        xhi, xlo, wqh, wql, qkv, BB * TT, QKVW, DM);
    // 2) chunk totals
    chunk_sums_tc<<<dim3(NCK, NBH), 256>>>();
    // 3) exclusive prefix
    chunk_prefix<<<dim3((STSZ + 255) / 256, NBH), 256>>>();
    // 4) intra-chunk attention (3 CTAs/SM)
    intra_tc<<<dim3(NCK, NBH), 256, IC3_SMEM>>>();
    // 5) out = xo @ Wout^T : same 64x128 kernel
    gemm_bf16_64<<<dim3(DM / 128, (BB * TT) / 64), 128, G1_SMEM>>>(
        xoh, xol, woh, wol, out, BB * TT, DM, DM);
}